// round 14
// baseline (speedup 1.0000x reference)
#include <cuda_runtime.h>
#include <math.h>
#include <stdint.h>

#define BSZ 2
#define SEQ 1024
#define DIM 1024
#define NH 16
#define FFD 4096
#define NL 2
#define RNK 16
#define VOC 32000
#define MT (BSZ*SEQ)
#define LORA_SCALE 2.0f
#define EPSV 1e-6f

#define P_W (NL*DIM*DIM/2)
#define P_F (NL*DIM*FFD/2)
#define P_L (DIM*VOC/2)
#define P_TOT (4*P_W + 2*P_F + P_L)

// GEMM: 4-stage pipeline, 16KB/stage -> 64KB/CTA -> 2 CTAs/SM (regs capped 128)
#define GS 4
#define STG_B 16384
#define SMEM_BYTES (GS*STG_B)

// attention smem: 8 planes x 64 rows x 9 chunks(16B) = 73728 B
#define AT_PL 9216
#define AT_SMEM (8*AT_PL)
#define PHALF ((size_t)BSZ*NH*SEQ*(SEQ/2))

// ---------------- scratch ----------------
__device__ float g_x[MT*DIM];
__device__ float g_tx[MT*DIM];
__device__ float g_h[MT*DIM];
__device__ float g_th[MT*DIM];
__device__ float g_q[MT*DIM];
__device__ float g_dq[MT*DIM];
__device__ float g_k[MT*DIM];
__device__ float g_dk[MT*DIM];
__device__ float g_v[MT*DIM];
__device__ float g_dv[MT*DIM];
__device__ float g_u[MT*FFD];
__device__ float g_du[MT*FFD];
__device__ float g_p[(size_t)BSZ*NH*SEQ*SEQ];
__device__ float g_dp[(size_t)BSZ*NH*SEQ*SEQ];
__device__ float g_cpq[MT*RNK];
__device__ float g_ctq[MT*RNK];
__device__ float g_cpv[MT*RNK];
__device__ float g_ctv[MT*RNK];
__device__ float g_dAq[NL*RNK*DIM];
__device__ float g_dBq[NL*DIM*RNK];
__device__ float g_dAv[NL*RNK*DIM];
__device__ float g_dBv[NL*DIM*RNK];

__device__ uint32_t g_hh[MT*DIM/2],  g_hl[MT*DIM/2];
__device__ uint32_t g_thh[MT*DIM/2], g_thl[MT*DIM/2];
__device__ uint32_t g_uh[MT*FFD/2],  g_ul[MT*FFD/2];
__device__ uint32_t g_duh[MT*FFD/2], g_dul[MT*FFD/2];
__device__ uint32_t g_oh[MT*DIM/2],  g_ol[MT*DIM/2];
__device__ uint32_t g_doh[MT*DIM/2], g_dol[MT*DIM/2];

// q/dq/k/dk/v/dv packed planes for MMA attention
__device__ uint32_t g_qph[MT*DIM/2],  g_qpl[MT*DIM/2];
__device__ uint32_t g_dqph[MT*DIM/2], g_dqpl[MT*DIM/2];
__device__ uint32_t g_kph[MT*DIM/2],  g_kpl[MT*DIM/2];
__device__ uint32_t g_dkph[MT*DIM/2], g_dkpl[MT*DIM/2];
__device__ uint32_t g_vph[MT*DIM/2],  g_vpl[MT*DIM/2];
__device__ uint32_t g_dvph[MT*DIM/2], g_dvpl[MT*DIM/2];

// packed softmax outputs (bf16 hi/lo planes of P and DP)
__device__ uint32_t g_pph[PHALF], g_ppl[PHALF];
__device__ uint32_t g_dpph[PHALF], g_dppl[PHALF];

// weights: bf16 hi/lo planes, B-transposed tile layout [K/16][N][8] u32
__device__ uint32_t g_wqh[P_W], g_wql[P_W];
__device__ uint32_t g_wkh[P_W], g_wkl[P_W];
__device__ uint32_t g_wvh[P_W], g_wvl[P_W];
__device__ uint32_t g_woh[P_W], g_wol[P_W];
__device__ uint32_t g_w1h[P_F], g_w1l[P_F];
__device__ uint32_t g_w2h[P_F], g_w2l[P_F];
__device__ uint32_t g_lmh[P_L], g_lml[P_L];

// ---------------- helpers ----------------
__device__ __forceinline__ uint32_t smem_u32(const void* p) {
    uint32_t a;
    asm("{ .reg .u64 t; cvta.to.shared.u64 t, %1; cvt.u32.u64 %0, t; }" : "=r"(a) : "l"(p));
    return a;
}
__device__ __forceinline__ void split2pair(float x0, float x1, uint32_t& hi, uint32_t& lo)
{
    uint32_t h;
    asm("cvt.rn.bf16x2.f32 %0, %1, %2;" : "=r"(h) : "f"(x1), "f"(x0));
    float h0 = __uint_as_float(h << 16);
    float h1 = __uint_as_float(h & 0xffff0000u);
    asm("cvt.rn.bf16x2.f32 %0, %1, %2;" : "=r"(lo) : "f"(x1 - h1), "f"(x0 - h0));
    hi = h;
}
__device__ __forceinline__ void mma_bf16(float c[4],
    uint32_t a0, uint32_t a1, uint32_t a2, uint32_t a3, uint32_t b0, uint32_t b1)
{
    asm volatile(
        "mma.sync.aligned.m16n8k16.row.col.f32.bf16.bf16.f32 "
        "{%0,%1,%2,%3}, {%4,%5,%6,%7}, {%8,%9}, {%0,%1,%2,%3};\n"
        : "+f"(c[0]), "+f"(c[1]), "+f"(c[2]), "+f"(c[3])
        : "r"(a0), "r"(a1), "r"(a2), "r"(a3), "r"(b0), "r"(b1));
}
__device__ __forceinline__ void ldsm4(uint32_t& r0, uint32_t& r1, uint32_t& r2, uint32_t& r3,
                                      uint32_t addr)
{
    asm volatile("ldmatrix.sync.aligned.m8n8.x4.shared.b16 {%0,%1,%2,%3}, [%4];"
                 : "=r"(r0), "=r"(r1), "=r"(r2), "=r"(r3) : "r"(addr));
}
__device__ __forceinline__ void ldsm4t(uint32_t& r0, uint32_t& r1, uint32_t& r2, uint32_t& r3,
                                       uint32_t addr)
{
    asm volatile("ldmatrix.sync.aligned.m8n8.x4.trans.shared.b16 {%0,%1,%2,%3}, [%4];"
                 : "=r"(r0), "=r"(r1), "=r"(r2), "=r"(r3) : "r"(addr));
}
__device__ __forceinline__ void cp16s(uint32_t s, const void* g) {
    asm volatile("cp.async.cg.shared.global [%0], [%1], 16;" :: "r"(s), "l"(g));
}
__device__ __forceinline__ uint32_t swz(int r, int c) {
    return (uint32_t)(r * 32 + ((c ^ ((r >> 2) & 1)) * 16));
}

// ---------------- ldmatrix bf16-split GEMM ----------------
// terms==3: full split (ah.bh + ah.bl + al.bh). terms==2: tangent path
// (A at plain bf16: ah.bh + ah.bl) — skips A-lo loads and MMAs.
__device__ __forceinline__ void gemm_core(
    const uint32_t* __restrict__ Ah, const uint32_t* __restrict__ Al,
    const uint32_t* __restrict__ Bh, const uint32_t* __restrict__ Bl,
    float* __restrict__ C, int Nfull, int K2, int accum, int row0, int col0, int terms)
{
    extern __shared__ uint32_t dsm[];
    const uint32_t sb = smem_u32(dsm);
    const int tid = threadIdx.x;
    const int wid = tid >> 5, lane = tid & 31;
    const int g = lane >> 2, t = lane & 3;
    const int wm = (wid >> 2) * 64;
    const int wn = (wid & 3) * 32;

    const int ld_r = tid >> 1, ld_c = tid & 1;
    const uint32_t st_off = swz(ld_r, ld_c);

    const uint32_t a_frag = swz(wm + (lane & 7) + ((lane >> 3) & 1) * 8, lane >> 4);
    const uint32_t b_frag = swz(wn + (lane & 7) + ((lane >> 4) & 1) * 8, (lane >> 3) & 1);

    float acc[4][4][4];
    #pragma unroll
    for (int mi = 0; mi < 4; mi++)
        #pragma unroll
        for (int ni = 0; ni < 4; ni++)
            #pragma unroll
            for (int e = 0; e < 4; e++) acc[mi][ni][e] = 0.f;

    const int nkt = K2 >> 3;
    #define LOAD_STAGE(KT, ST) do { \
        size_t aoff = (size_t)(row0 + ld_r) * K2 + (KT) * 8 + ld_c * 4; \
        size_t boff = ((size_t)(KT) * Nfull + col0 + ld_r) * 8 + ld_c * 4; \
        uint32_t s0 = sb + (ST) * STG_B + st_off; \
        cp16s(s0,         Ah + aoff); \
        if (terms == 3) cp16s(s0 + 4096, Al + aoff); \
        cp16s(s0 + 8192,  Bh + boff); \
        cp16s(s0 + 12288, Bl + boff); \
    } while (0)

    #pragma unroll
    for (int p = 0; p < GS - 1; p++) {
        LOAD_STAGE(p, p);
        asm volatile("cp.async.commit_group;");
    }

    int st_cur = 0, st_nxt = GS - 1;
    for (int kt = 0; kt < nkt; kt++) {
        asm volatile("cp.async.wait_group %0;" :: "n"(GS - 2));
        __syncthreads();
        if (kt + GS - 1 < nkt) {
            LOAD_STAGE(kt + GS - 1, st_nxt);
            if (++st_nxt == GS) st_nxt = 0;
        }
        asm volatile("cp.async.commit_group;");

        const uint32_t stb = sb + st_cur * STG_B;
        if (++st_cur == GS) st_cur = 0;
        uint32_t ah[4][4], al_[4][4], bh[4][2], bl_[4][2];
        #pragma unroll
        for (int mi = 0; mi < 4; mi++) {
            ldsm4(ah[mi][0], ah[mi][1], ah[mi][2], ah[mi][3], stb + a_frag + mi * 512);
            if (terms == 3)
                ldsm4(al_[mi][0], al_[mi][1], al_[mi][2], al_[mi][3],
                      stb + 4096 + a_frag + mi * 512);
        }
        #pragma unroll
        for (int p = 0; p < 2; p++) {
            ldsm4(bh[2*p][0], bh[2*p][1], bh[2*p+1][0], bh[2*p+1][1], stb + 8192 + b_frag + p * 512);
            ldsm4(bl_[2*p][0], bl_[2*p][1], bl_[2*p+1][0], bl_[2*p+1][1], stb + 12288 + b_frag + p * 512);
        }
        #pragma unroll
        for (int mi = 0; mi < 4; mi++)
            #pragma unroll
            for (int ni = 0; ni < 4; ni++) {
                mma_bf16(acc[mi][ni], ah[mi][0], ah[mi][1], ah[mi][2], ah[mi][3],
                         bh[ni][0], bh[ni][1]);
                mma_bf16(acc[mi][ni], ah[mi][0], ah[mi][1], ah[mi][2], ah[mi][3],
                         bl_[ni][0], bl_[ni][1]);
                if (terms == 3)
                    mma_bf16(acc[mi][ni], al_[mi][0], al_[mi][1], al_[mi][2], al_[mi][3],
                             bh[ni][0], bh[ni][1]);
            }
    }
    #undef LOAD_STAGE

    #pragma unroll
    for (int mi = 0; mi < 4; mi++) {
        int r = row0 + wm + mi * 16 + g;
        #pragma unroll
        for (int ni = 0; ni < 4; ni++) {
            int c = col0 + wn + ni * 8 + 2 * t;
            size_t i0 = (size_t)r * Nfull + c, i1 = (size_t)(r + 8) * Nfull + c;
            if (accum) {
                C[i0] += acc[mi][ni][0]; C[i0+1] += acc[mi][ni][1];
                C[i1] += acc[mi][ni][2]; C[i1+1] += acc[mi][ni][3];
            } else {
                C[i0] = acc[mi][ni][0]; C[i0+1] = acc[mi][ni][1];
                C[i1] = acc[mi][ni][2]; C[i1+1] = acc[mi][ni][3];
            }
        }
    }
}

// paired GEMM: z=0 primal (3-term), z=1 tangent (t2 terms)
__global__ __launch_bounds__(256, 2) void k_gemm_b2(
    const uint32_t* __restrict__ A1h, const uint32_t* __restrict__ A1l,
    const uint32_t* __restrict__ A2h, const uint32_t* __restrict__ A2l,
    const uint32_t* __restrict__ Bh, const uint32_t* __restrict__ Bl,
    float* __restrict__ C1, float* __restrict__ C2, int Nfull, int K2, int accum, int t2)
{
    gemm_core(blockIdx.z ? A2h : A1h, blockIdx.z ? A2l : A1l, Bh, Bl,
              blockIdx.z ? C2 : C1, Nfull, K2, accum, blockIdx.y * 128, blockIdx.x * 128,
              blockIdx.z ? t2 : 3);
}

__global__ __launch_bounds__(256, 2) void k_gemm_qkv(int loff)
{
    const int z = blockIdx.z;
    const uint32_t* Ah = (z & 1) ? g_thh : g_hh;
    const uint32_t* Al = (z & 1) ? g_thl : g_hl;
    const uint32_t *Bh, *Bl; float* C;
    const int w = z >> 1;
    if (w == 0)      { Bh = g_wqh + loff; Bl = g_wql + loff; C = (z & 1) ? g_dq : g_q; }
    else if (w == 1) { Bh = g_wkh + loff; Bl = g_wkl + loff; C = (z & 1) ? g_dk : g_k; }
    else             { Bh = g_wvh + loff; Bl = g_wvl + loff; C = (z & 1) ? g_dv : g_v; }
    gemm_core(Ah, Al, Bh, Bl, C, DIM, DIM / 2, 0, blockIdx.y * 128, blockIdx.x * 128,
              (z & 1) ? 2 : 3);
}

// ---------------- MMA NT attention: P = s*Q.K^T, DP = s*(dQ.K^T + Q.dK^T) ----------------
__global__ __launch_bounds__(256, 2) void k_attn_nt_mma(
    float* __restrict__ P, float* __restrict__ DP)
{
    const int bh = blockIdx.z, b = bh >> 4, h = bh & 15;
    const int i0 = blockIdx.y * 64, j0 = blockIdx.x * 64;
    if (j0 > i0) return;
    extern __shared__ uint32_t dsm[];
    const uint32_t sb = smem_u32(dsm);
    const int tid = threadIdx.x, wid = tid >> 5, lane = tid & 31;
    const uint32_t hoff32 = h * 32;

    const uint32_t* planes[8] = {g_qph, g_qpl, g_dqph, g_dqpl, g_kph, g_kpl, g_dkph, g_dkpl};
    for (int idx = tid; idx < 4096; idx += 256) {
        int pl = idx >> 9, wi = idx & 511, r = wi >> 3, c = wi & 7;
        int base = (pl < 4) ? i0 : j0;
        const uint32_t* src = planes[pl] + (size_t)(b * SEQ + base + r) * (DIM/2) + hoff32 + c * 4;
        cp16s(sb + pl * AT_PL + r * 144 + c * 16, src);
    }
    asm volatile("cp.async.commit_group;");
    asm volatile("cp.async.wait_group 0;");
    __syncthreads();

    const int wm = (wid & 3) * 16;
    const int wn = (wid >> 2) * 32;
    const uint32_t pQh = sb, pQl = sb + AT_PL, pdQh = sb + 2*AT_PL, pdQl = sb + 3*AT_PL;
    const uint32_t pKh = sb + 4*AT_PL, pKl = sb + 5*AT_PL, pdKh = sb + 6*AT_PL, pdKl = sb + 7*AT_PL;

    const int arow = wm + (lane & 7) + ((lane >> 3) & 1) * 8;
    const int brow = wn + (lane & 7) + ((lane >> 4) & 1) * 8;

    float accP[4][4], accD[4][4];
    #pragma unroll
    for (int ni = 0; ni < 4; ni++)
        #pragma unroll
        for (int e = 0; e < 4; e++) { accP[ni][e] = 0.f; accD[ni][e] = 0.f; }

    #pragma unroll
    for (int ks = 0; ks < 4; ks++) {
        const uint32_t aaddr = (uint32_t)(arow * 144 + (ks * 2 + (lane >> 4)) * 16);
        uint32_t qf[4], qlf[4], dqf[4], dqlf[4];
        ldsm4(qf[0], qf[1], qf[2], qf[3],     pQh  + aaddr);
        ldsm4(qlf[0], qlf[1], qlf[2], qlf[3], pQl  + aaddr);
        ldsm4(dqf[0], dqf[1], dqf[2], dqf[3], pdQh + aaddr);
        ldsm4(dqlf[0], dqlf[1], dqlf[2], dqlf[3], pdQl + aaddr);
        #pragma unroll
        for (int p = 0; p < 2; p++) {
            const uint32_t baddr = (uint32_t)((brow + p * 16) * 144
                                   + (ks * 2 + ((lane >> 3) & 1)) * 16);
            uint32_t kh[2][2], kl[2][2], dkh[2][2], dkl[2][2];
            ldsm4(kh[0][0], kh[0][1], kh[1][0], kh[1][1], pKh + baddr);
            ldsm4(kl[0][0], kl[0][1], kl[1][0], kl[1][1], pKl + baddr);
            ldsm4(dkh[0][0], dkh[0][1], dkh[1][0], dkh[1][1], pdKh + baddr);
            ldsm4(dkl[0][0], dkl[0][1], dkl[1][0], dkl[1][1], pdKl + baddr);
            #pragma unroll
            for (int q2 = 0; q2 < 2; q2++) {
                const int ni = p * 2 + q2;
                mma_bf16(accP[ni], qf[0], qf[1], qf[2], qf[3], kh[q2][0], kh[q2][1]);
                mma_bf16(accP[ni], qf[0], qf[1], qf[2], qf[3], kl[q2][0], kl[q2][1]);
                mma_bf16(accP[ni], qlf[0], qlf[1], qlf[2], qlf[3], kh[q2][0], kh[q2][1]);
                mma_bf16(accD[ni], dqf[0], dqf[1], dqf[2], dqf[3], kh[q2][0], kh[q2][1]);
                mma_bf16(accD[ni], dqf[0], dqf[1], dqf[2], dqf[3], kl[q2][0], kl[q2][1]);
                mma_bf16(accD[ni], dqlf[0], dqlf[1], dqlf[2], dqlf[3], kh[q2][0], kh[q2][1]);
                mma_bf16(accD[ni], qf[0], qf[1], qf[2], qf[3], dkh[q2][0], dkh[q2][1]);
                mma_bf16(accD[ni], qf[0], qf[1], qf[2], qf[3], dkl[q2][0], dkl[q2][1]);
                mma_bf16(accD[ni], qlf[0], qlf[1], qlf[2], qlf[3], dkh[q2][0], dkh[q2][1]);
            }
        }
    }

    const int g = lane >> 2, t = lane & 3;
    const size_t base = (size_t)bh * SEQ * SEQ;
    #pragma unroll
    for (int ni = 0; ni < 4; ni++) {
        int r = i0 + wm + g;
        int c = j0 + wn + ni * 8 + 2 * t;
        size_t o0 = base + (size_t)r * SEQ + c;
        size_t o1 = base + (size_t)(r + 8) * SEQ + c;
        P[o0]      = accP[ni][0] * 0.125f;
        P[o0 + 1]  = accP[ni][1] * 0.125f;
        P[o1]      = accP[ni][2] * 0.125f;
        P[o1 + 1]  = accP[ni][3] * 0.125f;
        DP[o0]     = accD[ni][0] * 0.125f;
        DP[o0 + 1] = accD[ni][1] * 0.125f;
        DP[o1]     = accD[ni][2] * 0.125f;
        DP[o1 + 1] = accD[ni][3] * 0.125f;
    }
}

// ---------------- MMA NN attention: o = P.V, do = DP.V + P.dV ----------------
__global__ __launch_bounds__(256, 2) void k_attn_nn_mma()
{
    const int bh = blockIdx.z, b = bh >> 4, h = bh & 15;
    const int i0 = blockIdx.y * 64;
    extern __shared__ uint32_t dsm[];
    const uint32_t sb = smem_u32(dsm);
    const int tid = threadIdx.x, wid = tid >> 5, lane = tid & 31;
    const uint32_t hoff32 = h * 32;
    const size_t pbase2 = (size_t)bh * SEQ * (SEQ/2);

    const int wm = (wid & 3) * 16;
    const int wn = (wid >> 2) * 32;
    const int arow = wm + (lane & 7) + ((lane >> 3) & 1) * 8;

    float accO[4][4], accD[4][4];
    #pragma unroll
    for (int ni = 0; ni < 4; ni++)
        #pragma unroll
        for (int e = 0; e < 4; e++) { accO[ni][e] = 0.f; accD[ni][e] = 0.f; }

    for (int k0 = 0; k0 <= i0; k0 += 64) {
        const uint32_t* pp[4] = {g_pph, g_ppl, g_dpph, g_dppl};
        const uint32_t* vv[4] = {g_vph, g_vpl, g_dvph, g_dvpl};
        for (int idx = tid; idx < 4096; idx += 256) {
            int pl = idx >> 9, wi = idx & 511, r = wi >> 3, c = wi & 7;
            const uint32_t* src;
            if (pl < 4)
                src = pp[pl] + pbase2 + (size_t)(i0 + r) * (SEQ/2) + (k0 >> 1) + c * 4;
            else
                src = vv[pl - 4] + (size_t)(b * SEQ + k0 + r) * (DIM/2) + hoff32 + c * 4;
            cp16s(sb + pl * AT_PL + r * 144 + c * 16, src);
        }
        asm volatile("cp.async.commit_group;");
        asm volatile("cp.async.wait_group 0;");
        __syncthreads();

        const uint32_t pPh = sb, pPl = sb + AT_PL, pDh = sb + 2*AT_PL, pDl = sb + 3*AT_PL;
        const uint32_t pVh = sb + 4*AT_PL, pVl = sb + 5*AT_PL;
        const uint32_t pdVh = sb + 6*AT_PL, pdVl = sb + 7*AT_PL;

        #pragma unroll
        for (int ks = 0; ks < 4; ks++) {
            const uint32_t aaddr = (uint32_t)(arow * 144 + (ks * 2 + (lane >> 4)) * 16);
            uint32_t pf[4], plf[4], df[4], dlf[4];
            ldsm4(pf[0], pf[1], pf[2], pf[3],     pPh + aaddr);
            ldsm4(plf[0], plf[1], plf[2], plf[3], pPl + aaddr);
            ldsm4(df[0], df[1], df[2], df[3],     pDh + aaddr);
            ldsm4(dlf[0], dlf[1], dlf[2], dlf[3], pDl + aaddr);
            const int krow = ks * 16 + (lane & 7) + ((lane >> 3) & 1) * 8;
            const int nc16 = (wn >> 3) + ((lane >> 4) & 1);
            #pragma unroll
            for (int p = 0; p < 2; p++) {
                const uint32_t baddr = (uint32_t)(krow * 144 + (nc16 + p * 2) * 16);
                uint32_t vh[2][2], vl[2][2], dvh[2][2], dvl[2][2];
                ldsm4t(vh[0][0], vh[0][1], vh[1][0], vh[1][1], pVh + baddr);
                ldsm4t(vl[0][0], vl[0][1], vl[1][0], vl[1][1], pVl + baddr);
                ldsm4t(dvh[0][0], dvh[0][1], dvh[1][0], dvh[1][1], pdVh + baddr);
                ldsm4t(dvl[0][0], dvl[0][1], dvl[1][0], dvl[1][1], pdVl + baddr);
                #pragma unroll
                for (int q2 = 0; q2 < 2; q2++) {
                    const int ni = p * 2 + q2;
                    mma_bf16(accO[ni], pf[0], pf[1], pf[2], pf[3], vh[q2][0], vh[q2][1]);
                    mma_bf16(accO[ni], pf[0], pf[1], pf[2], pf[3], vl[q2][0], vl[q2][1]);
                    mma_bf16(accO[ni], plf[0], plf[1], plf[2], plf[3], vh[q2][0], vh[q2][1]);
                    mma_bf16(accD[ni], df[0], df[1], df[2], df[3], vh[q2][0], vh[q2][1]);
                    mma_bf16(accD[ni], df[0], df[1], df[2], df[3], vl[q2][0], vl[q2][1]);
                    mma_bf16(accD[ni], dlf[0], dlf[1], dlf[2], dlf[3], vh[q2][0], vh[q2][1]);
                    mma_bf16(accD[ni], pf[0], pf[1], pf[2], pf[3], dvh[q2][0], dvh[q2][1]);
                    mma_bf16(accD[ni], pf[0], pf[1], pf[2], pf[3], dvl[q2][0], dvl[q2][1]);
                    mma_bf16(accD[ni], plf[0], plf[1], plf[2], plf[3], dvh[q2][0], dvh[q2][1]);
                }
            }
        }
        __syncthreads();
    }

    const int g = lane >> 2, t = lane & 3;
    #pragma unroll
    for (int ni = 0; ni < 4; ni++) {
        int r0 = b * SEQ + i0 + wm + g;
        size_t idx = hoff32 + (wn >> 1) + ni * 4 + t;
        uint32_t hi, lo;
        split2pair(accO[ni][0], accO[ni][1], hi, lo);
        g_oh[(size_t)r0 * (DIM/2) + idx] = hi;  g_ol[(size_t)r0 * (DIM/2) + idx] = lo;
        split2pair(accO[ni][2], accO[ni][3], hi, lo);
        g_oh[(size_t)(r0+8) * (DIM/2) + idx] = hi;  g_ol[(size_t)(r0+8) * (DIM/2) + idx] = lo;
        split2pair(accD[ni][0], accD[ni][1], hi, lo);
        g_doh[(size_t)r0 * (DIM/2) + idx] = hi; g_dol[(size_t)r0 * (DIM/2) + idx] = lo;
        split2pair(accD[ni][2], accD[ni][3], hi, lo);
        g_doh[(size_t)(r0+8) * (DIM/2) + idx] = hi; g_dol[(size_t)(r0+8) * (DIM/2) + idx] = lo;
    }
}

// split q/dq/k/dk/v/dv into packed bf16 hi/lo planes (after LoRA)
__global__ void k_split_act(const float* __restrict__ q, const float* __restrict__ dq,
                            const float* __restrict__ k, const float* __restrict__ dk,
                            const float* __restrict__ v, const float* __restrict__ dv)
{
    int i = blockIdx.x * 256 + threadIdx.x;
    size_t j = (size_t)i * 2;
    uint32_t hi, lo;
    float2 a = *reinterpret_cast<const float2*>(q + j);
    split2pair(a.x, a.y, hi, lo);  g_qph[i] = hi;  g_qpl[i] = lo;
    a = *reinterpret_cast<const float2*>(dq + j);
    split2pair(a.x, a.y, hi, lo);  g_dqph[i] = hi; g_dqpl[i] = lo;
    a = *reinterpret_cast<const float2*>(k + j);
    split2pair(a.x, a.y, hi, lo);  g_kph[i] = hi;  g_kpl[i] = lo;
    a = *reinterpret_cast<const float2*>(dk + j);
    split2pair(a.x, a.y, hi, lo);  g_dkph[i] = hi; g_dkpl[i] = lo;
    a = *reinterpret_cast<const float2*>(v + j);
    split2pair(a.x, a.y, hi, lo);  g_vph[i] = hi;  g_vpl[i] = lo;
    a = *reinterpret_cast<const float2*>(dv + j);
    split2pair(a.x, a.y, hi, lo);  g_dvph[i] = hi; g_dvpl[i] = lo;
}

// ---------------- setup ----------------
__global__ void k_embed(const int* __restrict__ ids, const float* __restrict__ emb,
                        float* __restrict__ x, float* __restrict__ tx)
{
    int i = blockIdx.x * 256 + threadIdx.x;
    x[i] = emb[(size_t)ids[i >> 10] * DIM + (i & 1023)];
    tx[i] = 0.f;
}

__global__ void k_diff_all(
    const float* __restrict__ Aq, const float* __restrict__ Aq0,
    const float* __restrict__ Bq, const float* __restrict__ Bq0,
    const float* __restrict__ Av, const float* __restrict__ Av0,
    const float* __restrict__ Bv, const float* __restrict__ Bv0,
    float* __restrict__ dAq, float* __restrict__ dBq,
    float* __restrict__ dAv, float* __restrict__ dBv)
{
    int i = blockIdx.x * 256 + threadIdx.x;
    int seg = i >> 15, j = i & 32767;
    if (seg == 0) dAq[j] = Aq[j] - Aq0[j];
    else if (seg == 1) dBq[j] = Bq[j] - Bq0[j];
    else if (seg == 2) dAv[j] = Av[j] - Av0[j];
    else dBv[j] = Bv[j] - Bv0[j];
}

// weights -> bf16 hi/lo planes, B-transposed tiles [K/16][N][8 u32]
__global__ void k_split_w(
    const float* __restrict__ Wq, const float* __restrict__ Wk,
    const float* __restrict__ Wv, const float* __restrict__ Wo,
    const float* __restrict__ W1, const float* __restrict__ W2,
    const float* __restrict__ Lm)
{
    long i = (long)blockIdx.x * 256 + threadIdx.x;
    if (i >= (long)P_TOT) return;
    const float* W; uint32_t *H, *L; unsigned p, N;
    if (i < 4L * P_W) {
        int seg = (int)(i >> 20);
        p = (unsigned)(i & (P_W - 1));
        N = DIM;
        if (seg == 0)      { W = Wq; H = g_wqh; L = g_wql; }
        else if (seg == 1) { W = Wk; H = g_wkh; L = g_wkl; }
        else if (seg == 2) { W = Wv; H = g_wvh; L = g_wvl; }
        else               { W = Wo; H = g_woh; L = g_wol; }
    } else if (i < 4L * P_W + 2L * P_F) {
        long j = i - 4L * P_W;
        p = (unsigned)(j & (P_F - 1));
        if (j < P_F) { W = W1; H = g_w1h; L = g_w1l; N = FFD; }
        else         { W = W2; H = g_w2h; L = g_w2l; N = DIM; }
    } else {
        p = (unsigned)(i - (4L * P_W + 2L * P_F));
        W = Lm; H = g_lmh; L = g_lml; N = VOC;
    }
    unsigned k2 = p / N, n = p - k2 * N;
    uint32_t hi, lo;
    split2pair(W[(size_t)(2*k2) * N + n], W[(size_t)(2*k2+1) * N + n], hi, lo);
    size_t op = (size_t)(k2 >> 3) * N * 8 + (size_t)n * 8 + (k2 & 7);
    H[op] = hi; L[op] = lo;
}

__global__ void k_rms(const float* __restrict__ X, const float* __restrict__ TX,
                      const float* __restrict__ g,
                      float* __restrict__ H, float* __restrict__ TH,
                      uint32_t* __restrict__ PH, uint32_t* __restrict__ PL,
                      uint32_t* __restrict__ PTH, uint32_t* __restrict__ PTL,
                      int combine)
{
    const int row = blockIdx.x, tid = threadIdx.x;
    const int d0 = tid * 4;
    float4 xv = *reinterpret_cast<const float4*>(X + (size_t)row * DIM + d0);
    float4 tv = *reinterpret_cast<const float4*>(TX + (size_t)row * DIM + d0);
    float ss = xv.x*xv.x + xv.y*xv.y + xv.z*xv.z + xv.w*xv.w;
    float st = xv.x*tv.x + xv.y*tv.y + xv.z*tv.z + xv.w*tv.w;
    __shared__ float sa[8], sb2[8];
    #pragma unroll
    for (int off = 16; off; off >>= 1) {
        ss += __shfl_down_sync(0xffffffffu, ss, off);
        st += __shfl_down_sync(0xffffffffu, st, off);
    }
    if ((tid & 31) == 0) { sa[tid >> 5] = ss; sb2[tid >> 5] = st; }
    __syncthreads();
    if (tid < 32) {
        float a = (tid < 8) ? sa[tid] : 0.f;
        float b = (tid < 8) ? sb2[tid] : 0.f;
        #pragma unroll
        for (int off = 4; off; off >>= 1) {
            a += __shfl_down_sync(0xffffffffu, a, off);
            b += __shfl_down_sync(0xffffffffu, b, off);
        }
        if (tid == 0) { sa[0] = a; sb2[0] = b; }
    }
    __syncthreads();
    const float m  = sa[0] * (1.f / DIM);
    const float mm = sb2[0] * (1.f / DIM);
    const float s  = 1.f / sqrtf(m + EPSV);
    const float s3mm = s * s * mm;
    float4 gv = *reinterpret_cast<const float4*>(g + d0);
    float h0 = gv.x*s*xv.x, h1 = gv.y*s*xv.y, h2 = gv.z*s*xv.z, h3 = gv.w*s*xv.w;
    float t0 = gv.x*s*(tv.x - xv.x*s3mm), t1 = gv.y*s*(tv.y - xv.y*s3mm);
    float t2 = gv.z*s*(tv.z - xv.z*s3mm), t3 = gv.w*s*(tv.w - xv.w*s3mm);
    const size_t pidx = (size_t)row * (DIM/2) + tid * 2;
    uint32_t hi, lo;
    if (combine) {
        split2pair(h0+t0, h1+t1, hi, lo); PH[pidx]   = hi; PL[pidx]   = lo;
        split2pair(h2+t2, h3+t3, hi, lo); PH[pidx+1] = hi; PL[pidx+1] = lo;
    } else {
        *reinterpret_cast<float4*>(H + (size_t)row * DIM + d0)  = make_float4(h0,h1,h2,h3);
        *reinterpret_cast<float4*>(TH + (size_t)row * DIM + d0) = make_float4(t0,t1,t2,t3);
        split2pair(h0, h1, hi, lo); PH[pidx]   = hi; PL[pidx]   = lo;
        split2pair(h2, h3, hi, lo); PH[pidx+1] = hi; PL[pidx+1] = lo;
        split2pair(t0, t1, hi, lo); PTH[pidx]   = hi; PTL[pidx]   = lo;
        split2pair(t2, t3, hi, lo); PTH[pidx+1] = hi; PTL[pidx+1] = lo;
    }
}

__global__ void k_gelu(const float* __restrict__ U, const float* __restrict__ DU,
                       uint32_t* __restrict__ UH, uint32_t* __restrict__ UL,
                       uint32_t* __restrict__ DUH, uint32_t* __restrict__ DUL)
{
    const int idx = blockIdx.x * 256 + threadIdx.x;
    const size_t i0 = (size_t)idx * 4;
    float4 uv = *reinterpret_cast<const float4*>(U + i0);
    float4 dv = *reinterpret_cast<const float4*>(DU + i0);
    float uu[4] = {uv.x, uv.y, uv.z, uv.w};
    float dd[4] = {dv.x, dv.y, dv.z, dv.w};
    float uo[4], duo[4];
    #pragma unroll
    for (int e = 0; e < 4; e++) {
        float u = uu[e], u2 = u*u;
        float w = 0.7978845608028654f * (u + 0.044715f * u * u2);
        float t = tanhf(w);
        float hp = 0.5f * (1.f + t);
        uo[e] = u * hp;
        duo[e] = dd[e] * (hp + 0.5f*u*(1.f-t*t)*0.7978845608028654f*(1.f+0.134145f*u2));
    }
    uint32_t hi, lo;
    const size_t p = (size_t)idx * 2;
    split2pair(uo[0], uo[1], hi, lo);  UH[p]   = hi; UL[p]   = lo;
    split2pair(uo[2], uo[3], hi, lo);  UH[p+1] = hi; UL[p+1] = lo;
    split2pair(duo[0], duo[1], hi, lo); DUH[p]   = hi; DUL[p]   = lo;
    split2pair(duo[2], duo[3], hi, lo); DUH[p+1] = hi; DUL[p+1] = lo;
}

// softmax + JVP; emits packed bf16 hi/lo planes of P and DP (zero-filled past diag)
__global__ void k_softmax(const float* __restrict__ P, const float* __restrict__ DS)
{
    const int i = blockIdx.x, bh = blockIdx.y;
    const float* p  = P  + (size_t)bh * SEQ * SEQ + (size_t)i * SEQ;
    const float* ds = DS + (size_t)bh * SEQ * SEQ + (size_t)i * SEQ;
    const int n = i + 1, tid = threadIdx.x;
    __shared__ float r0[8], r1[8], r2[8];
    float mx = -3.0e38f;
    for (int j = tid; j < n; j += 256) mx = fmaxf(mx, p[j]);
    #pragma unroll
    for (int off = 16; off; off >>= 1) mx = fmaxf(mx, __shfl_down_sync(0xffffffffu, mx, off));
    if ((tid & 31) == 0) r0[tid >> 5] = mx;
    __syncthreads();
    if (tid == 0) {
        float m = r0[0];
        for (int w = 1; w < 8; w++) m = fmaxf(m, r0[w]);
        r0[0] = m;
    }
    __syncthreads();
    const float m = r0[0];
    float s = 0.f, dt = 0.f;
    for (int j = tid; j < n; j += 256) {
        float e = expf(p[j] - m);
        s += e; dt += e * ds[j];
    }
    #pragma unroll
    for (int off = 16; off; off >>= 1) {
        s  += __shfl_down_sync(0xffffffffu, s, off);
        dt += __shfl_down_sync(0xffffffffu, dt, off);
    }
    if ((tid & 31) == 0) { r1[tid >> 5] = s; r2[tid >> 5] = dt; }
    __syncthreads();
    if (tid == 0) {
        float a = 0.f, bq = 0.f;
        for (int w = 0; w < 8; w++) { a += r1[w]; bq += r2[w]; }
        r1[0] = a; r2[0] = bq;
    }
    __syncthreads();
    const float inv = 1.f / r1[0];
    const float pd = r2[0] * inv;
    const size_t ob = (size_t)bh * SEQ * (SEQ/2) + (size_t)i * (SEQ/2);
    for (int j2 = tid; j2 < SEQ/2; j2 += 256) {
        int j = j2 * 2;
        float p0 = 0.f, p1 = 0.f, d0 = 0.f, d1 = 0.f;
        if (j < n) {
            p0 = expf(p[j] - m) * inv;
            d0 = p0 * (ds[j] - pd);
        }
        if (j + 1 < n) {
            p1 = expf(p[j+1] - m) * inv;
            d1 = p1 * (ds[j+1] - pd);
        }
        uint32_t hi, lo;
        split2pair(p0, p1, hi, lo); g_pph[ob + j2] = hi;  g_ppl[ob + j2] = lo;
        split2pair(d0, d1, hi, lo); g_dpph[ob + j2] = hi; g_dppl[ob + j2] = lo;
    }
}

// ---------------- fused LoRA ----------------
__global__ void k_lora_down4(const float* __restrict__ h, const float* __restrict__ th,
                             const float* __restrict__ aq0, const float* __restrict__ daq,
                             const float* __restrict__ av0, const float* __restrict__ dav)
{
    __shared__ float hs[DIM], ts[DIM];
    const int m = blockIdx.x, tid = threadIdx.x;
    #pragma unroll
    for (int e = 0; e < 4; e++) {
        int d = tid + e * 256;
        hs[d] = h[(size_t)m * DIM + d];
        ts[d] = th[(size_t)m * DIM + d];
    }
    __syncthreads();
    const int w = tid >> 5, lane = tid & 31;
    for (int task = w; task < 64; task += 8) {
        int r = task & 15, kind = task >> 4;
        const float* a  = (kind < 2) ? (aq0 + (size_t)r * DIM) : (av0 + (size_t)r * DIM);
        float s = 0.f;
        if ((kind & 1) == 0) {
            for (int d = lane; d < DIM; d += 32) s += hs[d] * a[d];
        } else {
            const float* da = (kind == 1) ? (daq + (size_t)r * DIM) : (dav + (size_t)r * DIM);
            for (int d = lane; d < DIM; d += 32) s += ts[d] * a[d] + hs[d] * da[d];
        }
        #pragma unroll
        for (int off = 16; off; off >>= 1) s += __shfl_down_sync(0xffffffffu, s, off);
        if (lane == 0) {
            float* o = (kind == 0) ? g_cpq : (kind == 1) ? g_ctq : (kind == 2) ? g_cpv : g_ctv;
            o[m * RNK + r] = s;
        }
    }
}

__global__ void k_lora_up2(float* __restrict__ q, float* __restrict__ dq,
                           float* __restrict__ v, float* __restrict__ dv,
                           const float* __restrict__ bq0, const float* __restrict__ dbq,
                           const float* __restrict__ bv0, const float* __restrict__ dbv)
{
    const int m = blockIdx.y;
    const int d = blockIdx.x * 256 + threadIdx.x;
    const int z = blockIdx.z;
    const float* c1 = z ? g_cpv : g_cpq;
    const float* c2 = z ? g_ctv : g_ctq;
    const float* B  = z ? bv0 : bq0;
    const float* dB = z ? dbv : dbq;
    float* C1 = z ? v : q;
    float* C2 = z ? dv : dq;
    __shared__ float s1[RNK], s2[RNK];
    if (threadIdx.x < RNK) {
        s1[threadIdx.x] = c1[m * RNK + threadIdx.x];
        s2[threadIdx.x] = c2[m * RNK + threadIdx.x];
    }
    __syncthreads();
    float a = 0.f, b = 0.f;
    const float* br  = B + (size_t)d * RNK;
    const float* dbr = dB + (size_t)d * RNK;
    #pragma unroll
    for (int r = 0; r < RNK; r++) {
        a += s1[r] * br[r];
        b += s2[r] * br[r] + s1[r] * dbr[r];
    }
    C1[(size_t)m * DIM + d] += LORA_SCALE * a;
    C2[(size_t)m * DIM + d] += LORA_SCALE * b;
}

// ---------------- host ----------------
extern "C" void kernel_launch(void* const* d_in, const int* in_sizes, int n_in,
                              void* d_out, int out_size)
{
    (void)in_sizes; (void)n_in; (void)out_size;
    const int*   ids = (const int*)  d_in[0];
    const float* emb = (const float*)d_in[1];
    const float* Wq  = (const float*)d_in[2];
    const float* Wk  = (const float*)d_in[3];
    const float* Wv  = (const float*)d_in[4];
    const float* Wo  = (const float*)d_in[5];
    const float* W1  = (const float*)d_in[6];
    const float* W2  = (const float*)d_in[7];
    const float* ln1 = (const float*)d_in[8];
    const float* ln2 = (const float*)d_in[9];
    const float* lnf = (const float*)d_in[10];
    const float* lm  = (const float*)d_in[11];
    const float* Aq0 = (const float*)d_in[12];
    const float* Bq0 = (const float*)d_in[13];
    const float* Av0 = (const float*)d_in[14];
    const float* Bv0 = (const float*)d_in[15];
    const float* Aq  = (const float*)d_in[16];
    const float* Bq  = (const float*)d_in[17];
    const float* Av  = (const float*)d_in[18];
    const float* Bv  = (const float*)d_in[19];
    float* out = (float*)d_out;

    cudaFuncSetAttribute(k_gemm_b2, cudaFuncAttributeMaxDynamicSharedMemorySize, SMEM_BYTES);
    cudaFuncSetAttribute(k_gemm_qkv, cudaFuncAttributeMaxDynamicSharedMemorySize, SMEM_BYTES);
    cudaFuncSetAttribute(k_attn_nt_mma, cudaFuncAttributeMaxDynamicSharedMemorySize, AT_SMEM);
    cudaFuncSetAttribute(k_attn_nn_mma, cudaFuncAttributeMaxDynamicSharedMemorySize, AT_SMEM);

    float *x,*tx,*h,*th,*q,*dq,*k,*dk,*v,*dv,*u,*du,*P,*DP;
    float *dAq,*dBq,*dAv,*dBv;
    uint32_t *hh,*hl,*thh,*thl,*uh,*ul,*duh,*dul,*oh,*ol,*doh,*dol;
    uint32_t *w1h,*w1l,*w2h,*w2l,*woh,*wol,*lmh,*lml;
    cudaGetSymbolAddress((void**)&x, g_x);   cudaGetSymbolAddress((void**)&tx, g_tx);
    cudaGetSymbolAddress((void**)&h, g_h);   cudaGetSymbolAddress((void**)&th, g_th);
    cudaGetSymbolAddress((void**)&q, g_q);   cudaGetSymbolAddress((void**)&dq, g_dq);
    cudaGetSymbolAddress((void**)&k, g_k);   cudaGetSymbolAddress((void**)&dk, g_dk);
    cudaGetSymbolAddress((void**)&v, g_v);   cudaGetSymbolAddress((void**)&dv, g_dv);
    cudaGetSymbolAddress((void**)&u, g_u);   cudaGetSymbolAddress((void**)&du, g_du);
    cudaGetSymbolAddress((void**)&P, g_p);   cudaGetSymbolAddress((void**)&DP, g_dp);
    cudaGetSymbolAddress((void**)&dAq, g_dAq); cudaGetSymbolAddress((void**)&dBq, g_dBq);
    cudaGetSymbolAddress((void**)&dAv, g_dAv); cudaGetSymbolAddress((void**)&dBv, g_dBv);
    cudaGetSymbolAddress((void**)&hh, g_hh);   cudaGetSymbolAddress((void**)&hl, g_hl);
    cudaGetSymbolAddress((void**)&thh, g_thh); cudaGetSymbolAddress((void**)&thl, g_thl);
    cudaGetSymbolAddress((void**)&uh, g_uh);   cudaGetSymbolAddress((void**)&ul, g_ul);
    cudaGetSymbolAddress((void**)&duh, g_duh); cudaGetSymbolAddress((void**)&dul, g_dul);
    cudaGetSymbolAddress((void**)&oh, g_oh);   cudaGetSymbolAddress((void**)&ol, g_ol);
    cudaGetSymbolAddress((void**)&doh, g_doh); cudaGetSymbolAddress((void**)&dol, g_dol);
    cudaGetSymbolAddress((void**)&w1h, g_w1h); cudaGetSymbolAddress((void**)&w1l, g_w1l);
    cudaGetSymbolAddress((void**)&w2h, g_w2h); cudaGetSymbolAddress((void**)&w2l, g_w2l);
    cudaGetSymbolAddress((void**)&woh, g_woh); cudaGetSymbolAddress((void**)&wol, g_wol);
    cudaGetSymbolAddress((void**)&lmh, g_lmh); cudaGetSymbolAddress((void**)&lml, g_lml);

    const dim3 gD2(DIM/128, MT/128, 2);
    const dim3 gF2(FFD/128, MT/128, 2);
    const dim3 gV1(VOC/128, MT/128, 1);
    const dim3 gQKV(DIM/128, MT/128, 6);
    const dim3 gNT(SEQ/64, SEQ/64, BSZ*NH);
    const dim3 gNN(1, SEQ/64, BSZ*NH);
    const dim3 gLU2(DIM/256, MT, 2);

    k_embed<<<MT*DIM/256, 256>>>(ids, emb, x, tx);
    k_rms<<<MT, 256>>>(x, tx, ln1, h, th, hh, hl, thh, thl, 0);
    k_split_w<<<(P_TOT + 255)/256, 256>>>(Wq, Wk, Wv, Wo, W1, W2, lm);
    k_gemm_qkv<<<gQKV, 256, SMEM_BYTES>>>(0);
    k_diff_all<<<4*32768/256, 256>>>(Aq, Aq0, Bq, Bq0, Av, Av0, Bv, Bv0, dAq, dBq, dAv, dBv);

    for (int l = 0; l < NL; l++) {
        const int loffD = l * (DIM*DIM/2);
        const int loffF = l * (DIM*FFD/2);
        const float* aq0 = Aq0 + (size_t)l*RNK*DIM;
        const float* bq0 = Bq0 + (size_t)l*DIM*RNK;
        const float* av0 = Av0 + (size_t)l*RNK*DIM;
        const float* bv0 = Bv0 + (size_t)l*DIM*RNK;
        const float* daq = dAq + (size_t)l*RNK*DIM;
        const float* dbq = dBq + (size_t)l*DIM*RNK;
        const float* dav = dAv + (size_t)l*RNK*DIM;
        const float* dbv = dBv + (size_t)l*DIM*RNK;

        if (l > 0) {
            k_rms<<<MT, 256>>>(x, tx, ln1 + l*DIM, h, th, hh, hl, thh, thl, 0);
            k_gemm_qkv<<<gQKV, 256, SMEM_BYTES>>>(loffD);
        }

        k_lora_down4<<<MT, 256>>>(h, th, aq0, daq, av0, dav);
        k_lora_up2<<<gLU2, 256>>>(q, dq, v, dv, bq0, dbq, bv0, dbv);

        k_split_act<<<MT*DIM/512, 256>>>(q, dq, k, dk, v, dv);
        k_attn_nt_mma<<<gNT, 256, AT_SMEM>>>(P, DP);
        k_softmax<<<dim3(SEQ, BSZ*NH), 256>>>(P, DP);
        k_attn_nn_mma<<<gNN, 256, AT_SMEM>>>();

        k_gemm_b2<<<gD2, 256, SMEM_BYTES>>>(oh, ol, doh, dol,
            woh + loffD, wol + loffD, x, tx, DIM, DIM/2, 1, 2);

        k_rms<<<MT, 256>>>(x, tx, ln2 + l*DIM, h, th, hh, hl, thh, thl, 0);
        k_gemm_b2<<<gF2, 256, SMEM_BYTES>>>(hh, hl, thh, thl,
            w1h + loffF, w1l + loffF, u, du, FFD, DIM/2, 0, 2);
        k_gelu<<<MT*FFD/1024, 256>>>(u, du, uh, ul, duh, dul);
        k_gemm_b2<<<gD2, 256, SMEM_BYTES>>>(uh, ul, duh, dul,
            w2h + loffF, w2l + loffF, x, tx, DIM, FFD/2, 1, 2);
    }

    // final norm: z = rms(x) + rms_jvp (packed bf16), then bf16-split lm_head
    k_rms<<<MT, 256>>>(x, tx, lnf, nullptr, nullptr, hh, hl, nullptr, nullptr, 1);
    k_gemm_b2<<<gV1, 256, SMEM_BYTES>>>(hh, hl, hh, hl, lmh, lml,
        out, out, VOC, DIM/2, 0, 3);
}

// round 15
// speedup vs baseline: 1.0097x; 1.0097x over previous
#include <cuda_runtime.h>
#include <math.h>
#include <stdint.h>

#define BSZ 2
#define SEQ 1024
#define DIM 1024
#define NH 16
#define FFD 4096
#define NL 2
#define RNK 16
#define VOC 32000
#define MT (BSZ*SEQ)
#define LORA_SCALE 2.0f
#define EPSV 1e-6f

#define P_W (NL*DIM*DIM/2)
#define P_F (NL*DIM*FFD/2)
#define P_L (DIM*VOC/2)
#define P_TOT (4*P_W + 2*P_F + P_L)

// GEMM: 4-stage pipeline, 16KB/stage -> 64KB/CTA -> 2 CTAs/SM (regs capped 128)
#define GS 4
#define STG_B 16384
#define SMEM_BYTES (GS*STG_B)

// attention smem: 8 planes x 64 rows x 9 chunks(16B) = 73728 B
#define AT_PL 9216
#define AT_SMEM (8*AT_PL)
#define PHALF ((size_t)BSZ*NH*SEQ*(SEQ/2))

// ---------------- scratch ----------------
__device__ float g_x[MT*DIM];
__device__ float g_tx[MT*DIM];
__device__ float g_h[MT*DIM];
__device__ float g_th[MT*DIM];
__device__ float g_q[MT*DIM];
__device__ float g_dq[MT*DIM];
__device__ float g_k[MT*DIM];
__device__ float g_dk[MT*DIM];
__device__ float g_v[MT*DIM];
__device__ float g_dv[MT*DIM];
__device__ float g_u[MT*FFD];
__device__ float g_du[MT*FFD];
__device__ float g_p[(size_t)BSZ*NH*SEQ*SEQ];
__device__ float g_dp[(size_t)BSZ*NH*SEQ*SEQ];
__device__ float g_cpq[MT*RNK];
__device__ float g_ctq[MT*RNK];
__device__ float g_cpv[MT*RNK];
__device__ float g_ctv[MT*RNK];
__device__ float g_dAq[NL*RNK*DIM];
__device__ float g_dBq[NL*DIM*RNK];
__device__ float g_dAv[NL*RNK*DIM];
__device__ float g_dBv[NL*DIM*RNK];

__device__ uint32_t g_hh[MT*DIM/2],  g_hl[MT*DIM/2];
__device__ uint32_t g_thh[MT*DIM/2], g_thl[MT*DIM/2];
__device__ uint32_t g_uh[MT*FFD/2],  g_ul[MT*FFD/2];
__device__ uint32_t g_duh[MT*FFD/2], g_dul[MT*FFD/2];
__device__ uint32_t g_oh[MT*DIM/2],  g_ol[MT*DIM/2];
__device__ uint32_t g_doh[MT*DIM/2], g_dol[MT*DIM/2];

// q/dq/k/dk/v/dv packed planes for MMA attention
__device__ uint32_t g_qph[MT*DIM/2],  g_qpl[MT*DIM/2];
__device__ uint32_t g_dqph[MT*DIM/2], g_dqpl[MT*DIM/2];
__device__ uint32_t g_kph[MT*DIM/2],  g_kpl[MT*DIM/2];
__device__ uint32_t g_dkph[MT*DIM/2], g_dkpl[MT*DIM/2];
__device__ uint32_t g_vph[MT*DIM/2],  g_vpl[MT*DIM/2];
__device__ uint32_t g_dvph[MT*DIM/2], g_dvpl[MT*DIM/2];

// packed softmax outputs (bf16 hi/lo planes of P and DP)
__device__ uint32_t g_pph[PHALF], g_ppl[PHALF];
__device__ uint32_t g_dpph[PHALF], g_dppl[PHALF];

// weights: bf16 hi/lo planes, B-transposed tile layout [K/16][N][8] u32
__device__ uint32_t g_wqh[P_W], g_wql[P_W];
__device__ uint32_t g_wkh[P_W], g_wkl[P_W];
__device__ uint32_t g_wvh[P_W], g_wvl[P_W];
__device__ uint32_t g_woh[P_W], g_wol[P_W];
__device__ uint32_t g_w1h[P_F], g_w1l[P_F];
__device__ uint32_t g_w2h[P_F], g_w2l[P_F];
__device__ uint32_t g_lmh[P_L], g_lml[P_L];

// ---------------- helpers ----------------
__device__ __forceinline__ uint32_t smem_u32(const void* p) {
    uint32_t a;
    asm("{ .reg .u64 t; cvta.to.shared.u64 t, %1; cvt.u32.u64 %0, t; }" : "=r"(a) : "l"(p));
    return a;
}
__device__ __forceinline__ void split2pair(float x0, float x1, uint32_t& hi, uint32_t& lo)
{
    uint32_t h;
    asm("cvt.rn.bf16x2.f32 %0, %1, %2;" : "=r"(h) : "f"(x1), "f"(x0));
    float h0 = __uint_as_float(h << 16);
    float h1 = __uint_as_float(h & 0xffff0000u);
    asm("cvt.rn.bf16x2.f32 %0, %1, %2;" : "=r"(lo) : "f"(x1 - h1), "f"(x0 - h0));
    hi = h;
}
__device__ __forceinline__ void mma_bf16(float c[4],
    uint32_t a0, uint32_t a1, uint32_t a2, uint32_t a3, uint32_t b0, uint32_t b1)
{
    asm volatile(
        "mma.sync.aligned.m16n8k16.row.col.f32.bf16.bf16.f32 "
        "{%0,%1,%2,%3}, {%4,%5,%6,%7}, {%8,%9}, {%0,%1,%2,%3};\n"
        : "+f"(c[0]), "+f"(c[1]), "+f"(c[2]), "+f"(c[3])
        : "r"(a0), "r"(a1), "r"(a2), "r"(a3), "r"(b0), "r"(b1));
}
__device__ __forceinline__ void ldsm4(uint32_t& r0, uint32_t& r1, uint32_t& r2, uint32_t& r3,
                                      uint32_t addr)
{
    asm volatile("ldmatrix.sync.aligned.m8n8.x4.shared.b16 {%0,%1,%2,%3}, [%4];"
                 : "=r"(r0), "=r"(r1), "=r"(r2), "=r"(r3) : "r"(addr));
}
__device__ __forceinline__ void ldsm4t(uint32_t& r0, uint32_t& r1, uint32_t& r2, uint32_t& r3,
                                       uint32_t addr)
{
    asm volatile("ldmatrix.sync.aligned.m8n8.x4.trans.shared.b16 {%0,%1,%2,%3}, [%4];"
                 : "=r"(r0), "=r"(r1), "=r"(r2), "=r"(r3) : "r"(addr));
}
__device__ __forceinline__ void cp16s(uint32_t s, const void* g) {
    asm volatile("cp.async.cg.shared.global [%0], [%1], 16;" :: "r"(s), "l"(g));
}
__device__ __forceinline__ uint32_t swz(int r, int c) {
    return (uint32_t)(r * 32 + ((c ^ ((r >> 2) & 1)) * 16));
}

// ---------------- ldmatrix bf16-split GEMM (full 3-term, R12-proven) ----------------
__device__ __forceinline__ void gemm_core(
    const uint32_t* __restrict__ Ah, const uint32_t* __restrict__ Al,
    const uint32_t* __restrict__ Bh, const uint32_t* __restrict__ Bl,
    float* __restrict__ C, int Nfull, int K2, int accum, int row0, int col0)
{
    extern __shared__ uint32_t dsm[];
    const uint32_t sb = smem_u32(dsm);
    const int tid = threadIdx.x;
    const int wid = tid >> 5, lane = tid & 31;
    const int g = lane >> 2, t = lane & 3;
    const int wm = (wid >> 2) * 64;
    const int wn = (wid & 3) * 32;

    const int ld_r = tid >> 1, ld_c = tid & 1;
    const uint32_t st_off = swz(ld_r, ld_c);

    const uint32_t a_frag = swz(wm + (lane & 7) + ((lane >> 3) & 1) * 8, lane >> 4);
    const uint32_t b_frag = swz(wn + (lane & 7) + ((lane >> 4) & 1) * 8, (lane >> 3) & 1);

    float acc[4][4][4];
    #pragma unroll
    for (int mi = 0; mi < 4; mi++)
        #pragma unroll
        for (int ni = 0; ni < 4; ni++)
            #pragma unroll
            for (int e = 0; e < 4; e++) acc[mi][ni][e] = 0.f;

    const int nkt = K2 >> 3;
    #define LOAD_STAGE(KT, ST) do { \
        size_t aoff = (size_t)(row0 + ld_r) * K2 + (KT) * 8 + ld_c * 4; \
        size_t boff = ((size_t)(KT) * Nfull + col0 + ld_r) * 8 + ld_c * 4; \
        uint32_t s0 = sb + (ST) * STG_B + st_off; \
        cp16s(s0,         Ah + aoff); \
        cp16s(s0 + 4096,  Al + aoff); \
        cp16s(s0 + 8192,  Bh + boff); \
        cp16s(s0 + 12288, Bl + boff); \
    } while (0)

    #pragma unroll
    for (int p = 0; p < GS - 1; p++) {
        LOAD_STAGE(p, p);
        asm volatile("cp.async.commit_group;");
    }

    int st_cur = 0, st_nxt = GS - 1;
    for (int kt = 0; kt < nkt; kt++) {
        asm volatile("cp.async.wait_group %0;" :: "n"(GS - 2));
        __syncthreads();
        if (kt + GS - 1 < nkt) {
            LOAD_STAGE(kt + GS - 1, st_nxt);
            if (++st_nxt == GS) st_nxt = 0;
        }
        asm volatile("cp.async.commit_group;");

        const uint32_t stb = sb + st_cur * STG_B;
        if (++st_cur == GS) st_cur = 0;
        uint32_t ah[4][4], al_[4][4], bh[4][2], bl_[4][2];
        #pragma unroll
        for (int mi = 0; mi < 4; mi++) {
            ldsm4(ah[mi][0], ah[mi][1], ah[mi][2], ah[mi][3], stb + a_frag + mi * 512);
            ldsm4(al_[mi][0], al_[mi][1], al_[mi][2], al_[mi][3], stb + 4096 + a_frag + mi * 512);
        }
        #pragma unroll
        for (int p = 0; p < 2; p++) {
            ldsm4(bh[2*p][0], bh[2*p][1], bh[2*p+1][0], bh[2*p+1][1], stb + 8192 + b_frag + p * 512);
            ldsm4(bl_[2*p][0], bl_[2*p][1], bl_[2*p+1][0], bl_[2*p+1][1], stb + 12288 + b_frag + p * 512);
        }
        #pragma unroll
        for (int mi = 0; mi < 4; mi++)
            #pragma unroll
            for (int ni = 0; ni < 4; ni++) {
                mma_bf16(acc[mi][ni], ah[mi][0], ah[mi][1], ah[mi][2], ah[mi][3],
                         bh[ni][0], bh[ni][1]);
                mma_bf16(acc[mi][ni], ah[mi][0], ah[mi][1], ah[mi][2], ah[mi][3],
                         bl_[ni][0], bl_[ni][1]);
                mma_bf16(acc[mi][ni], al_[mi][0], al_[mi][1], al_[mi][2], al_[mi][3],
                         bh[ni][0], bh[ni][1]);
            }
    }
    #undef LOAD_STAGE

    #pragma unroll
    for (int mi = 0; mi < 4; mi++) {
        int r = row0 + wm + mi * 16 + g;
        #pragma unroll
        for (int ni = 0; ni < 4; ni++) {
            int c = col0 + wn + ni * 8 + 2 * t;
            size_t i0 = (size_t)r * Nfull + c, i1 = (size_t)(r + 8) * Nfull + c;
            if (accum) {
                C[i0] += acc[mi][ni][0]; C[i0+1] += acc[mi][ni][1];
                C[i1] += acc[mi][ni][2]; C[i1+1] += acc[mi][ni][3];
            } else {
                C[i0] = acc[mi][ni][0]; C[i0+1] = acc[mi][ni][1];
                C[i1] = acc[mi][ni][2]; C[i1+1] = acc[mi][ni][3];
            }
        }
    }
}

__global__ __launch_bounds__(256, 2) void k_gemm_b2(
    const uint32_t* __restrict__ A1h, const uint32_t* __restrict__ A1l,
    const uint32_t* __restrict__ A2h, const uint32_t* __restrict__ A2l,
    const uint32_t* __restrict__ Bh, const uint32_t* __restrict__ Bl,
    float* __restrict__ C1, float* __restrict__ C2, int Nfull, int K2, int accum)
{
    gemm_core(blockIdx.z ? A2h : A1h, blockIdx.z ? A2l : A1l, Bh, Bl,
              blockIdx.z ? C2 : C1, Nfull, K2, accum, blockIdx.y * 128, blockIdx.x * 128);
}

// lm_head: row-blocks fastest so a wave shares B column slices via L2
__global__ __launch_bounds__(256, 2) void k_gemm_lmw(float* __restrict__ C)
{
    gemm_core(g_hh, g_hl, g_lmh, g_lml, C, VOC, DIM / 2, 0,
              blockIdx.x * 128, blockIdx.y * 128);
}

__global__ __launch_bounds__(256, 2) void k_gemm_qkv(int loff)
{
    const int z = blockIdx.z;
    const uint32_t* Ah = (z & 1) ? g_thh : g_hh;
    const uint32_t* Al = (z & 1) ? g_thl : g_hl;
    const uint32_t *Bh, *Bl; float* C;
    const int w = z >> 1;
    if (w == 0)      { Bh = g_wqh + loff; Bl = g_wql + loff; C = (z & 1) ? g_dq : g_q; }
    else if (w == 1) { Bh = g_wkh + loff; Bl = g_wkl + loff; C = (z & 1) ? g_dk : g_k; }
    else             { Bh = g_wvh + loff; Bl = g_wvl + loff; C = (z & 1) ? g_dv : g_v; }
    gemm_core(Ah, Al, Bh, Bl, C, DIM, DIM / 2, 0, blockIdx.y * 128, blockIdx.x * 128);
}

// ---------------- MMA NT attention: P = s*Q.K^T, DP = s*(dQ.K^T + Q.dK^T) ----------------
__global__ __launch_bounds__(256, 2) void k_attn_nt_mma(
    float* __restrict__ P, float* __restrict__ DP)
{
    const int bh = blockIdx.z, b = bh >> 4, h = bh & 15;
    const int i0 = blockIdx.y * 64, j0 = blockIdx.x * 64;
    if (j0 > i0) return;
    extern __shared__ uint32_t dsm[];
    const uint32_t sb = smem_u32(dsm);
    const int tid = threadIdx.x, wid = tid >> 5, lane = tid & 31;
    const uint32_t hoff32 = h * 32;

    const uint32_t* planes[8] = {g_qph, g_qpl, g_dqph, g_dqpl, g_kph, g_kpl, g_dkph, g_dkpl};
    for (int idx = tid; idx < 4096; idx += 256) {
        int pl = idx >> 9, wi = idx & 511, r = wi >> 3, c = wi & 7;
        int base = (pl < 4) ? i0 : j0;
        const uint32_t* src = planes[pl] + (size_t)(b * SEQ + base + r) * (DIM/2) + hoff32 + c * 4;
        cp16s(sb + pl * AT_PL + r * 144 + c * 16, src);
    }
    asm volatile("cp.async.commit_group;");
    asm volatile("cp.async.wait_group 0;");
    __syncthreads();

    const int wm = (wid & 3) * 16;
    const int wn = (wid >> 2) * 32;
    const uint32_t pQh = sb, pQl = sb + AT_PL, pdQh = sb + 2*AT_PL, pdQl = sb + 3*AT_PL;
    const uint32_t pKh = sb + 4*AT_PL, pKl = sb + 5*AT_PL, pdKh = sb + 6*AT_PL, pdKl = sb + 7*AT_PL;

    const int arow = wm + (lane & 7) + ((lane >> 3) & 1) * 8;
    const int brow = wn + (lane & 7) + ((lane >> 4) & 1) * 8;

    float accP[4][4], accD[4][4];
    #pragma unroll
    for (int ni = 0; ni < 4; ni++)
        #pragma unroll
        for (int e = 0; e < 4; e++) { accP[ni][e] = 0.f; accD[ni][e] = 0.f; }

    #pragma unroll
    for (int ks = 0; ks < 4; ks++) {
        const uint32_t aaddr = (uint32_t)(arow * 144 + (ks * 2 + (lane >> 4)) * 16);
        uint32_t qf[4], qlf[4], dqf[4], dqlf[4];
        ldsm4(qf[0], qf[1], qf[2], qf[3],     pQh  + aaddr);
        ldsm4(qlf[0], qlf[1], qlf[2], qlf[3], pQl  + aaddr);
        ldsm4(dqf[0], dqf[1], dqf[2], dqf[3], pdQh + aaddr);
        ldsm4(dqlf[0], dqlf[1], dqlf[2], dqlf[3], pdQl + aaddr);
        #pragma unroll
        for (int p = 0; p < 2; p++) {
            const uint32_t baddr = (uint32_t)((brow + p * 16) * 144
                                   + (ks * 2 + ((lane >> 3) & 1)) * 16);
            uint32_t kh[2][2], kl[2][2], dkh[2][2], dkl[2][2];
            ldsm4(kh[0][0], kh[0][1], kh[1][0], kh[1][1], pKh + baddr);
            ldsm4(kl[0][0], kl[0][1], kl[1][0], kl[1][1], pKl + baddr);
            ldsm4(dkh[0][0], dkh[0][1], dkh[1][0], dkh[1][1], pdKh + baddr);
            ldsm4(dkl[0][0], dkl[0][1], dkl[1][0], dkl[1][1], pdKl + baddr);
            #pragma unroll
            for (int q2 = 0; q2 < 2; q2++) {
                const int ni = p * 2 + q2;
                mma_bf16(accP[ni], qf[0], qf[1], qf[2], qf[3], kh[q2][0], kh[q2][1]);
                mma_bf16(accP[ni], qf[0], qf[1], qf[2], qf[3], kl[q2][0], kl[q2][1]);
                mma_bf16(accP[ni], qlf[0], qlf[1], qlf[2], qlf[3], kh[q2][0], kh[q2][1]);
                mma_bf16(accD[ni], dqf[0], dqf[1], dqf[2], dqf[3], kh[q2][0], kh[q2][1]);
                mma_bf16(accD[ni], dqf[0], dqf[1], dqf[2], dqf[3], kl[q2][0], kl[q2][1]);
                mma_bf16(accD[ni], dqlf[0], dqlf[1], dqlf[2], dqlf[3], kh[q2][0], kh[q2][1]);
                mma_bf16(accD[ni], qf[0], qf[1], qf[2], qf[3], dkh[q2][0], dkh[q2][1]);
                mma_bf16(accD[ni], qf[0], qf[1], qf[2], qf[3], dkl[q2][0], dkl[q2][1]);
                mma_bf16(accD[ni], qlf[0], qlf[1], qlf[2], qlf[3], dkh[q2][0], dkh[q2][1]);
            }
        }
    }

    const int g = lane >> 2, t = lane & 3;
    const size_t base = (size_t)bh * SEQ * SEQ;
    #pragma unroll
    for (int ni = 0; ni < 4; ni++) {
        int r = i0 + wm + g;
        int c = j0 + wn + ni * 8 + 2 * t;
        size_t o0 = base + (size_t)r * SEQ + c;
        size_t o1 = base + (size_t)(r + 8) * SEQ + c;
        P[o0]      = accP[ni][0] * 0.125f;
        P[o0 + 1]  = accP[ni][1] * 0.125f;
        P[o1]      = accP[ni][2] * 0.125f;
        P[o1 + 1]  = accP[ni][3] * 0.125f;
        DP[o0]     = accD[ni][0] * 0.125f;
        DP[o0 + 1] = accD[ni][1] * 0.125f;
        DP[o1]     = accD[ni][2] * 0.125f;
        DP[o1 + 1] = accD[ni][3] * 0.125f;
    }
}

// ---------------- MMA NN attention: o = P.V, do = DP.V + P.dV ----------------
__global__ __launch_bounds__(256, 2) void k_attn_nn_mma()
{
    const int bh = blockIdx.z, b = bh >> 4, h = bh & 15;
    const int i0 = blockIdx.y * 64;
    extern __shared__ uint32_t dsm[];
    const uint32_t sb = smem_u32(dsm);
    const int tid = threadIdx.x, wid = tid >> 5, lane = tid & 31;
    const uint32_t hoff32 = h * 32;
    const size_t pbase2 = (size_t)bh * SEQ * (SEQ/2);

    const int wm = (wid & 3) * 16;
    const int wn = (wid >> 2) * 32;
    const int arow = wm + (lane & 7) + ((lane >> 3) & 1) * 8;

    float accO[4][4], accD[4][4];
    #pragma unroll
    for (int ni = 0; ni < 4; ni++)
        #pragma unroll
        for (int e = 0; e < 4; e++) { accO[ni][e] = 0.f; accD[ni][e] = 0.f; }

    for (int k0 = 0; k0 <= i0; k0 += 64) {
        const uint32_t* pp[4] = {g_pph, g_ppl, g_dpph, g_dppl};
        const uint32_t* vv[4] = {g_vph, g_vpl, g_dvph, g_dvpl};
        for (int idx = tid; idx < 4096; idx += 256) {
            int pl = idx >> 9, wi = idx & 511, r = wi >> 3, c = wi & 7;
            const uint32_t* src;
            if (pl < 4)
                src = pp[pl] + pbase2 + (size_t)(i0 + r) * (SEQ/2) + (k0 >> 1) + c * 4;
            else
                src = vv[pl - 4] + (size_t)(b * SEQ + k0 + r) * (DIM/2) + hoff32 + c * 4;
            cp16s(sb + pl * AT_PL + r * 144 + c * 16, src);
        }
        asm volatile("cp.async.commit_group;");
        asm volatile("cp.async.wait_group 0;");
        __syncthreads();

        const uint32_t pPh = sb, pPl = sb + AT_PL, pDh = sb + 2*AT_PL, pDl = sb + 3*AT_PL;
        const uint32_t pVh = sb + 4*AT_PL, pVl = sb + 5*AT_PL;
        const uint32_t pdVh = sb + 6*AT_PL, pdVl = sb + 7*AT_PL;

        #pragma unroll
        for (int ks = 0; ks < 4; ks++) {
            const uint32_t aaddr = (uint32_t)(arow * 144 + (ks * 2 + (lane >> 4)) * 16);
            uint32_t pf[4], plf[4], df[4], dlf[4];
            ldsm4(pf[0], pf[1], pf[2], pf[3],     pPh + aaddr);
            ldsm4(plf[0], plf[1], plf[2], plf[3], pPl + aaddr);
            ldsm4(df[0], df[1], df[2], df[3],     pDh + aaddr);
            ldsm4(dlf[0], dlf[1], dlf[2], dlf[3], pDl + aaddr);
            const int krow = ks * 16 + (lane & 7) + ((lane >> 3) & 1) * 8;
            const int nc16 = (wn >> 3) + ((lane >> 4) & 1);
            #pragma unroll
            for (int p = 0; p < 2; p++) {
                const uint32_t baddr = (uint32_t)(krow * 144 + (nc16 + p * 2) * 16);
                uint32_t vh[2][2], vl[2][2], dvh[2][2], dvl[2][2];
                ldsm4t(vh[0][0], vh[0][1], vh[1][0], vh[1][1], pVh + baddr);
                ldsm4t(vl[0][0], vl[0][1], vl[1][0], vl[1][1], pVl + baddr);
                ldsm4t(dvh[0][0], dvh[0][1], dvh[1][0], dvh[1][1], pdVh + baddr);
                ldsm4t(dvl[0][0], dvl[0][1], dvl[1][0], dvl[1][1], pdVl + baddr);
                #pragma unroll
                for (int q2 = 0; q2 < 2; q2++) {
                    const int ni = p * 2 + q2;
                    mma_bf16(accO[ni], pf[0], pf[1], pf[2], pf[3], vh[q2][0], vh[q2][1]);
                    mma_bf16(accO[ni], pf[0], pf[1], pf[2], pf[3], vl[q2][0], vl[q2][1]);
                    mma_bf16(accO[ni], plf[0], plf[1], plf[2], plf[3], vh[q2][0], vh[q2][1]);
                    mma_bf16(accD[ni], df[0], df[1], df[2], df[3], vh[q2][0], vh[q2][1]);
                    mma_bf16(accD[ni], df[0], df[1], df[2], df[3], vl[q2][0], vl[q2][1]);
                    mma_bf16(accD[ni], dlf[0], dlf[1], dlf[2], dlf[3], vh[q2][0], vh[q2][1]);
                    mma_bf16(accD[ni], pf[0], pf[1], pf[2], pf[3], dvh[q2][0], dvh[q2][1]);
                    mma_bf16(accD[ni], pf[0], pf[1], pf[2], pf[3], dvl[q2][0], dvl[q2][1]);
                    mma_bf16(accD[ni], plf[0], plf[1], plf[2], plf[3], dvh[q2][0], dvh[q2][1]);
                }
            }
        }
        __syncthreads();
    }

    const int g = lane >> 2, t = lane & 3;
    #pragma unroll
    for (int ni = 0; ni < 4; ni++) {
        int r0 = b * SEQ + i0 + wm + g;
        size_t idx = hoff32 + (wn >> 1) + ni * 4 + t;
        uint32_t hi, lo;
        split2pair(accO[ni][0], accO[ni][1], hi, lo);
        g_oh[(size_t)r0 * (DIM/2) + idx] = hi;  g_ol[(size_t)r0 * (DIM/2) + idx] = lo;
        split2pair(accO[ni][2], accO[ni][3], hi, lo);
        g_oh[(size_t)(r0+8) * (DIM/2) + idx] = hi;  g_ol[(size_t)(r0+8) * (DIM/2) + idx] = lo;
        split2pair(accD[ni][0], accD[ni][1], hi, lo);
        g_doh[(size_t)r0 * (DIM/2) + idx] = hi; g_dol[(size_t)r0 * (DIM/2) + idx] = lo;
        split2pair(accD[ni][2], accD[ni][3], hi, lo);
        g_doh[(size_t)(r0+8) * (DIM/2) + idx] = hi; g_dol[(size_t)(r0+8) * (DIM/2) + idx] = lo;
    }
}

// split q/dq/k/dk/v/dv into packed bf16 hi/lo planes (after LoRA)
__global__ void k_split_act(const float* __restrict__ q, const float* __restrict__ dq,
                            const float* __restrict__ k, const float* __restrict__ dk,
                            const float* __restrict__ v, const float* __restrict__ dv)
{
    int i = blockIdx.x * 256 + threadIdx.x;
    size_t j = (size_t)i * 2;
    uint32_t hi, lo;
    float2 a = *reinterpret_cast<const float2*>(q + j);
    split2pair(a.x, a.y, hi, lo);  g_qph[i] = hi;  g_qpl[i] = lo;
    a = *reinterpret_cast<const float2*>(dq + j);
    split2pair(a.x, a.y, hi, lo);  g_dqph[i] = hi; g_dqpl[i] = lo;
    a = *reinterpret_cast<const float2*>(k + j);
    split2pair(a.x, a.y, hi, lo);  g_kph[i] = hi;  g_kpl[i] = lo;
    a = *reinterpret_cast<const float2*>(dk + j);
    split2pair(a.x, a.y, hi, lo);  g_dkph[i] = hi; g_dkpl[i] = lo;
    a = *reinterpret_cast<const float2*>(v + j);
    split2pair(a.x, a.y, hi, lo);  g_vph[i] = hi;  g_vpl[i] = lo;
    a = *reinterpret_cast<const float2*>(dv + j);
    split2pair(a.x, a.y, hi, lo);  g_dvph[i] = hi; g_dvpl[i] = lo;
}

// ---------------- setup ----------------
__global__ void k_embed(const int* __restrict__ ids, const float* __restrict__ emb,
                        float* __restrict__ x, float* __restrict__ tx)
{
    int i = blockIdx.x * 256 + threadIdx.x;
    x[i] = emb[(size_t)ids[i >> 10] * DIM + (i & 1023)];
    tx[i] = 0.f;
}

__global__ void k_diff_all(
    const float* __restrict__ Aq, const float* __restrict__ Aq0,
    const float* __restrict__ Bq, const float* __restrict__ Bq0,
    const float* __restrict__ Av, const float* __restrict__ Av0,
    const float* __restrict__ Bv, const float* __restrict__ Bv0,
    float* __restrict__ dAq, float* __restrict__ dBq,
    float* __restrict__ dAv, float* __restrict__ dBv)
{
    int i = blockIdx.x * 256 + threadIdx.x;
    int seg = i >> 15, j = i & 32767;
    if (seg == 0) dAq[j] = Aq[j] - Aq0[j];
    else if (seg == 1) dBq[j] = Bq[j] - Bq0[j];
    else if (seg == 2) dAv[j] = Av[j] - Av0[j];
    else dBv[j] = Bv[j] - Bv0[j];
}

// weights -> bf16 hi/lo planes, B-transposed tiles [K/16][N][8 u32]
__global__ void k_split_w(
    const float* __restrict__ Wq, const float* __restrict__ Wk,
    const float* __restrict__ Wv, const float* __restrict__ Wo,
    const float* __restrict__ W1, const float* __restrict__ W2,
    const float* __restrict__ Lm)
{
    long i = (long)blockIdx.x * 256 + threadIdx.x;
    if (i >= (long)P_TOT) return;
    const float* W; uint32_t *H, *L; unsigned p, N;
    if (i < 4L * P_W) {
        int seg = (int)(i >> 20);
        p = (unsigned)(i & (P_W - 1));
        N = DIM;
        if (seg == 0)      { W = Wq; H = g_wqh; L = g_wql; }
        else if (seg == 1) { W = Wk; H = g_wkh; L = g_wkl; }
        else if (seg == 2) { W = Wv; H = g_wvh; L = g_wvl; }
        else               { W = Wo; H = g_woh; L = g_wol; }
    } else if (i < 4L * P_W + 2L * P_F) {
        long j = i - 4L * P_W;
        p = (unsigned)(j & (P_F - 1));
        if (j < P_F) { W = W1; H = g_w1h; L = g_w1l; N = FFD; }
        else         { W = W2; H = g_w2h; L = g_w2l; N = DIM; }
    } else {
        p = (unsigned)(i - (4L * P_W + 2L * P_F));
        W = Lm; H = g_lmh; L = g_lml; N = VOC;
    }
    unsigned k2 = p / N, n = p - k2 * N;
    uint32_t hi, lo;
    split2pair(W[(size_t)(2*k2) * N + n], W[(size_t)(2*k2+1) * N + n], hi, lo);
    size_t op = (size_t)(k2 >> 3) * N * 8 + (size_t)n * 8 + (k2 & 7);
    H[op] = hi; L[op] = lo;
}

__global__ void k_rms(const float* __restrict__ X, const float* __restrict__ TX,
                      const float* __restrict__ g,
                      float* __restrict__ H, float* __restrict__ TH,
                      uint32_t* __restrict__ PH, uint32_t* __restrict__ PL,
                      uint32_t* __restrict__ PTH, uint32_t* __restrict__ PTL,
                      int combine)
{
    const int row = blockIdx.x, tid = threadIdx.x;
    const int d0 = tid * 4;
    float4 xv = *reinterpret_cast<const float4*>(X + (size_t)row * DIM + d0);
    float4 tv = *reinterpret_cast<const float4*>(TX + (size_t)row * DIM + d0);
    float ss = xv.x*xv.x + xv.y*xv.y + xv.z*xv.z + xv.w*xv.w;
    float st = xv.x*tv.x + xv.y*tv.y + xv.z*tv.z + xv.w*tv.w;
    __shared__ float sa[8], sb2[8];
    #pragma unroll
    for (int off = 16; off; off >>= 1) {
        ss += __shfl_down_sync(0xffffffffu, ss, off);
        st += __shfl_down_sync(0xffffffffu, st, off);
    }
    if ((tid & 31) == 0) { sa[tid >> 5] = ss; sb2[tid >> 5] = st; }
    __syncthreads();
    if (tid < 32) {
        float a = (tid < 8) ? sa[tid] : 0.f;
        float b = (tid < 8) ? sb2[tid] : 0.f;
        #pragma unroll
        for (int off = 4; off; off >>= 1) {
            a += __shfl_down_sync(0xffffffffu, a, off);
            b += __shfl_down_sync(0xffffffffu, b, off);
        }
        if (tid == 0) { sa[0] = a; sb2[0] = b; }
    }
    __syncthreads();
    const float m  = sa[0] * (1.f / DIM);
    const float mm = sb2[0] * (1.f / DIM);
    const float s  = 1.f / sqrtf(m + EPSV);
    const float s3mm = s * s * mm;
    float4 gv = *reinterpret_cast<const float4*>(g + d0);
    float h0 = gv.x*s*xv.x, h1 = gv.y*s*xv.y, h2 = gv.z*s*xv.z, h3 = gv.w*s*xv.w;
    float t0 = gv.x*s*(tv.x - xv.x*s3mm), t1 = gv.y*s*(tv.y - xv.y*s3mm);
    float t2 = gv.z*s*(tv.z - xv.z*s3mm), t3 = gv.w*s*(tv.w - xv.w*s3mm);
    const size_t pidx = (size_t)row * (DIM/2) + tid * 2;
    uint32_t hi, lo;
    if (combine) {
        split2pair(h0+t0, h1+t1, hi, lo); PH[pidx]   = hi; PL[pidx]   = lo;
        split2pair(h2+t2, h3+t3, hi, lo); PH[pidx+1] = hi; PL[pidx+1] = lo;
    } else {
        *reinterpret_cast<float4*>(H + (size_t)row * DIM + d0)  = make_float4(h0,h1,h2,h3);
        *reinterpret_cast<float4*>(TH + (size_t)row * DIM + d0) = make_float4(t0,t1,t2,t3);
        split2pair(h0, h1, hi, lo); PH[pidx]   = hi; PL[pidx]   = lo;
        split2pair(h2, h3, hi, lo); PH[pidx+1] = hi; PL[pidx+1] = lo;
        split2pair(t0, t1, hi, lo); PTH[pidx]   = hi; PTL[pidx]   = lo;
        split2pair(t2, t3, hi, lo); PTH[pidx+1] = hi; PTL[pidx+1] = lo;
    }
}

__global__ void k_gelu(const float* __restrict__ U, const float* __restrict__ DU,
                       uint32_t* __restrict__ UH, uint32_t* __restrict__ UL,
                       uint32_t* __restrict__ DUH, uint32_t* __restrict__ DUL)
{
    const int idx = blockIdx.x * 256 + threadIdx.x;
    const size_t i0 = (size_t)idx * 4;
    float4 uv = *reinterpret_cast<const float4*>(U + i0);
    float4 dv = *reinterpret_cast<const float4*>(DU + i0);
    float uu[4] = {uv.x, uv.y, uv.z, uv.w};
    float dd[4] = {dv.x, dv.y, dv.z, dv.w};
    float uo[4], duo[4];
    #pragma unroll
    for (int e = 0; e < 4; e++) {
        float u = uu[e], u2 = u*u;
        float w = 0.7978845608028654f * (u + 0.044715f * u * u2);
        float t = tanhf(w);
        float hp = 0.5f * (1.f + t);
        uo[e] = u * hp;
        duo[e] = dd[e] * (hp + 0.5f*u*(1.f-t*t)*0.7978845608028654f*(1.f+0.134145f*u2));
    }
    uint32_t hi, lo;
    const size_t p = (size_t)idx * 2;
    split2pair(uo[0], uo[1], hi, lo);  UH[p]   = hi; UL[p]   = lo;
    split2pair(uo[2], uo[3], hi, lo);  UH[p+1] = hi; UL[p+1] = lo;
    split2pair(duo[0], duo[1], hi, lo); DUH[p]   = hi; DUL[p]   = lo;
    split2pair(duo[2], duo[3], hi, lo); DUH[p+1] = hi; DUL[p+1] = lo;
}

// softmax + JVP; smem-cached row (single gmem read), emits packed bf16 planes
__global__ void k_softmax(const float* __restrict__ P, const float* __restrict__ DS)
{
    const int i = blockIdx.x, bh = blockIdx.y;
    const float* p  = P  + (size_t)bh * SEQ * SEQ + (size_t)i * SEQ;
    const float* ds = DS + (size_t)bh * SEQ * SEQ + (size_t)i * SEQ;
    const int n = i + 1, tid = threadIdx.x;
    __shared__ float sp[SEQ], sds[SEQ];
    __shared__ float r0[8], r1[8], r2[8];

    float mx = -3.0e38f;
    for (int j = tid; j < n; j += 256) {
        float v = p[j];
        sp[j] = v;
        sds[j] = ds[j];
        mx = fmaxf(mx, v);
    }
    #pragma unroll
    for (int off = 16; off; off >>= 1) mx = fmaxf(mx, __shfl_down_sync(0xffffffffu, mx, off));
    if ((tid & 31) == 0) r0[tid >> 5] = mx;
    __syncthreads();
    if (tid == 0) {
        float m = r0[0];
        for (int w = 1; w < 8; w++) m = fmaxf(m, r0[w]);
        r0[0] = m;
    }
    __syncthreads();
    const float m = r0[0];
    float s = 0.f, dt = 0.f;
    for (int j = tid; j < n; j += 256) {
        float e = expf(sp[j] - m);
        sp[j] = e;                      // store exp for final pass
        s += e; dt += e * sds[j];
    }
    #pragma unroll
    for (int off = 16; off; off >>= 1) {
        s  += __shfl_down_sync(0xffffffffu, s, off);
        dt += __shfl_down_sync(0xffffffffu, dt, off);
    }
    if ((tid & 31) == 0) { r1[tid >> 5] = s; r2[tid >> 5] = dt; }
    __syncthreads();
    if (tid == 0) {
        float a = 0.f, bq = 0.f;
        for (int w = 0; w < 8; w++) { a += r1[w]; bq += r2[w]; }
        r1[0] = a; r2[0] = bq;
    }
    __syncthreads();
    const float inv = 1.f / r1[0];
    const float pd = r2[0] * inv;
    const size_t ob = (size_t)bh * SEQ * (SEQ/2) + (size_t)i * (SEQ/2);
    for (int j2 = tid; j2 < SEQ/2; j2 += 256) {
        int j = j2 * 2;
        float p0 = 0.f, p1 = 0.f, d0 = 0.f, d1 = 0.f;
        if (j < n) {
            p0 = sp[j] * inv;
            d0 = p0 * (sds[j] - pd);
        }
        if (j + 1 < n) {
            p1 = sp[j+1] * inv;
            d1 = p1 * (sds[j+1] - pd);
        }
        uint32_t hi, lo;
        split2pair(p0, p1, hi, lo); g_pph[ob + j2] = hi;  g_ppl[ob + j2] = lo;
        split2pair(d0, d1, hi, lo); g_dpph[ob + j2] = hi; g_dppl[ob + j2] = lo;
    }
}

// ---------------- fused LoRA ----------------
__global__ void k_lora_down4(const float* __restrict__ h, const float* __restrict__ th,
                             const float* __restrict__ aq0, const float* __restrict__ daq,
                             const float* __restrict__ av0, const float* __restrict__ dav)
{
    __shared__ float hs[DIM], ts[DIM];
    const int m = blockIdx.x, tid = threadIdx.x;
    #pragma unroll
    for (int e = 0; e < 4; e++) {
        int d = tid + e * 256;
        hs[d] = h[(size_t)m * DIM + d];
        ts[d] = th[(size_t)m * DIM + d];
    }
    __syncthreads();
    const int w = tid >> 5, lane = tid & 31;
    for (int task = w; task < 64; task += 8) {
        int r = task & 15, kind = task >> 4;
        const float* a  = (kind < 2) ? (aq0 + (size_t)r * DIM) : (av0 + (size_t)r * DIM);
        float s = 0.f;
        if ((kind & 1) == 0) {
            for (int d = lane; d < DIM; d += 32) s += hs[d] * a[d];
        } else {
            const float* da = (kind == 1) ? (daq + (size_t)r * DIM) : (dav + (size_t)r * DIM);
            for (int d = lane; d < DIM; d += 32) s += ts[d] * a[d] + hs[d] * da[d];
        }
        #pragma unroll
        for (int off = 16; off; off >>= 1) s += __shfl_down_sync(0xffffffffu, s, off);
        if (lane == 0) {
            float* o = (kind == 0) ? g_cpq : (kind == 1) ? g_ctq : (kind == 2) ? g_cpv : g_ctv;
            o[m * RNK + r] = s;
        }
    }
}

__global__ void k_lora_up2(float* __restrict__ q, float* __restrict__ dq,
                           float* __restrict__ v, float* __restrict__ dv,
                           const float* __restrict__ bq0, const float* __restrict__ dbq,
                           const float* __restrict__ bv0, const float* __restrict__ dbv)
{
    const int m = blockIdx.y;
    const int d = blockIdx.x * 256 + threadIdx.x;
    const int z = blockIdx.z;
    const float* c1 = z ? g_cpv : g_cpq;
    const float* c2 = z ? g_ctv : g_ctq;
    const float* B  = z ? bv0 : bq0;
    const float* dB = z ? dbv : dbq;
    float* C1 = z ? v : q;
    float* C2 = z ? dv : dq;
    __shared__ float s1[RNK], s2[RNK];
    if (threadIdx.x < RNK) {
        s1[threadIdx.x] = c1[m * RNK + threadIdx.x];
        s2[threadIdx.x] = c2[m * RNK + threadIdx.x];
    }
    __syncthreads();
    float a = 0.f, b = 0.f;
    const float* br  = B + (size_t)d * RNK;
    const float* dbr = dB + (size_t)d * RNK;
    #pragma unroll
    for (int r = 0; r < RNK; r++) {
        a += s1[r] * br[r];
        b += s2[r] * br[r] + s1[r] * dbr[r];
    }
    C1[(size_t)m * DIM + d] += LORA_SCALE * a;
    C2[(size_t)m * DIM + d] += LORA_SCALE * b;
}

// ---------------- host ----------------
extern "C" void kernel_launch(void* const* d_in, const int* in_sizes, int n_in,
                              void* d_out, int out_size)
{
    (void)in_sizes; (void)n_in; (void)out_size;
    const int*   ids = (const int*)  d_in[0];
    const float* emb = (const float*)d_in[1];
    const float* Wq  = (const float*)d_in[2];
    const float* Wk  = (const float*)d_in[3];
    const float* Wv  = (const float*)d_in[4];
    const float* Wo  = (const float*)d_in[5];
    const float* W1  = (const float*)d_in[6];
    const float* W2  = (const float*)d_in[7];
    const float* ln1 = (const float*)d_in[8];
    const float* ln2 = (const float*)d_in[9];
    const float* lnf = (const float*)d_in[10];
    const float* lm  = (const float*)d_in[11];
    const float* Aq0 = (const float*)d_in[12];
    const float* Bq0 = (const float*)d_in[13];
    const float* Av0 = (const float*)d_in[14];
    const float* Bv0 = (const float*)d_in[15];
    const float* Aq  = (const float*)d_in[16];
    const float* Bq  = (const float*)d_in[17];
    const float* Av  = (const float*)d_in[18];
    const float* Bv  = (const float*)d_in[19];
    float* out = (float*)d_out;

    cudaFuncSetAttribute(k_gemm_b2, cudaFuncAttributeMaxDynamicSharedMemorySize, SMEM_BYTES);
    cudaFuncSetAttribute(k_gemm_lmw, cudaFuncAttributeMaxDynamicSharedMemorySize, SMEM_BYTES);
    cudaFuncSetAttribute(k_gemm_qkv, cudaFuncAttributeMaxDynamicSharedMemorySize, SMEM_BYTES);
    cudaFuncSetAttribute(k_attn_nt_mma, cudaFuncAttributeMaxDynamicSharedMemorySize, AT_SMEM);
    cudaFuncSetAttribute(k_attn_nn_mma, cudaFuncAttributeMaxDynamicSharedMemorySize, AT_SMEM);

    float *x,*tx,*h,*th,*q,*dq,*k,*dk,*v,*dv,*u,*du,*P,*DP;
    float *dAq,*dBq,*dAv,*dBv;
    uint32_t *hh,*hl,*thh,*thl,*uh,*ul,*duh,*dul,*oh,*ol,*doh,*dol;
    uint32_t *w1h,*w1l,*w2h,*w2l,*woh,*wol;
    cudaGetSymbolAddress((void**)&x, g_x);   cudaGetSymbolAddress((void**)&tx, g_tx);
    cudaGetSymbolAddress((void**)&h, g_h);   cudaGetSymbolAddress((void**)&th, g_th);
    cudaGetSymbolAddress((void**)&q, g_q);   cudaGetSymbolAddress((void**)&dq, g_dq);
    cudaGetSymbolAddress((void**)&k, g_k);   cudaGetSymbolAddress((void**)&dk, g_dk);
    cudaGetSymbolAddress((void**)&v, g_v);   cudaGetSymbolAddress((void**)&dv, g_dv);
    cudaGetSymbolAddress((void**)&u, g_u);   cudaGetSymbolAddress((void**)&du, g_du);
    cudaGetSymbolAddress((void**)&P, g_p);   cudaGetSymbolAddress((void**)&DP, g_dp);
    cudaGetSymbolAddress((void**)&dAq, g_dAq); cudaGetSymbolAddress((void**)&dBq, g_dBq);
    cudaGetSymbolAddress((void**)&dAv, g_dAv); cudaGetSymbolAddress((void**)&dBv, g_dBv);
    cudaGetSymbolAddress((void**)&hh, g_hh);   cudaGetSymbolAddress((void**)&hl, g_hl);
    cudaGetSymbolAddress((void**)&thh, g_thh); cudaGetSymbolAddress((void**)&thl, g_thl);
    cudaGetSymbolAddress((void**)&uh, g_uh);   cudaGetSymbolAddress((void**)&ul, g_ul);
    cudaGetSymbolAddress((void**)&duh, g_duh); cudaGetSymbolAddress((void**)&dul, g_dul);
    cudaGetSymbolAddress((void**)&oh, g_oh);   cudaGetSymbolAddress((void**)&ol, g_ol);
    cudaGetSymbolAddress((void**)&doh, g_doh); cudaGetSymbolAddress((void**)&dol, g_dol);
    cudaGetSymbolAddress((void**)&w1h, g_w1h); cudaGetSymbolAddress((void**)&w1l, g_w1l);
    cudaGetSymbolAddress((void**)&w2h, g_w2h); cudaGetSymbolAddress((void**)&w2l, g_w2l);
    cudaGetSymbolAddress((void**)&woh, g_woh); cudaGetSymbolAddress((void**)&wol, g_wol);

    const dim3 gD2(DIM/128, MT/128, 2);
    const dim3 gF2(FFD/128, MT/128, 2);
    const dim3 gLM(MT/128, VOC/128, 1);     // row-blocks fastest: B slices shared per wave
    const dim3 gQKV(DIM/128, MT/128, 6);
    const dim3 gNT(SEQ/64, SEQ/64, BSZ*NH);
    const dim3 gNN(1, SEQ/64, BSZ*NH);
    const dim3 gLU2(DIM/256, MT, 2);

    k_embed<<<MT*DIM/256, 256>>>(ids, emb, x, tx);
    k_rms<<<MT, 256>>>(x, tx, ln1, h, th, hh, hl, thh, thl, 0);
    k_split_w<<<(P_TOT + 255)/256, 256>>>(Wq, Wk, Wv, Wo, W1, W2, lm);
    k_gemm_qkv<<<gQKV, 256, SMEM_BYTES>>>(0);
    k_diff_all<<<4*32768/256, 256>>>(Aq, Aq0, Bq, Bq0, Av, Av0, Bv, Bv0, dAq, dBq, dAv, dBv);

    for (int l = 0; l < NL; l++) {
        const int loffD = l * (DIM*DIM/2);
        const int loffF = l * (DIM*FFD/2);
        const float* aq0 = Aq0 + (size_t)l*RNK*DIM;
        const float* bq0 = Bq0 + (size_t)l*DIM*RNK;
        const float* av0 = Av0 + (size_t)l*RNK*DIM;
        const float* bv0 = Bv0 + (size_t)l*DIM*RNK;
        const float* daq = dAq + (size_t)l*RNK*DIM;
        const float* dbq = dBq + (size_t)l*DIM*RNK;
        const float* dav = dAv + (size_t)l*RNK*DIM;
        const float* dbv = dBv + (size_t)l*DIM*RNK;

        if (l > 0) {
            k_rms<<<MT, 256>>>(x, tx, ln1 + l*DIM, h, th, hh, hl, thh, thl, 0);
            k_gemm_qkv<<<gQKV, 256, SMEM_BYTES>>>(loffD);
        }

        k_lora_down4<<<MT, 256>>>(h, th, aq0, daq, av0, dav);
        k_lora_up2<<<gLU2, 256>>>(q, dq, v, dv, bq0, dbq, bv0, dbv);

        k_split_act<<<MT*DIM/512, 256>>>(q, dq, k, dk, v, dv);
        k_attn_nt_mma<<<gNT, 256, AT_SMEM>>>(P, DP);
        k_softmax<<<dim3(SEQ, BSZ*NH), 256>>>(P, DP);
        k_attn_nn_mma<<<gNN, 256, AT_SMEM>>>();

        k_gemm_b2<<<gD2, 256, SMEM_BYTES>>>(oh, ol, doh, dol,
            woh + loffD, wol + loffD, x, tx, DIM, DIM/2, 1);

        k_rms<<<MT, 256>>>(x, tx, ln2 + l*DIM, h, th, hh, hl, thh, thl, 0);
        k_gemm_b2<<<gF2, 256, SMEM_BYTES>>>(hh, hl, thh, thl,
            w1h + loffF, w1l + loffF, u, du, FFD, DIM/2, 0);
        k_gelu<<<MT*FFD/1024, 256>>>(u, du, uh, ul, duh, dul);
        k_gemm_b2<<<gD2, 256, SMEM_BYTES>>>(uh, ul, duh, dul,
            w2h + loffF, w2l + loffF, x, tx, DIM, FFD/2, 1);
    }

    // final norm: z = rms(x) + rms_jvp (packed bf16), then bf16-split lm_head
    k_rms<<<MT, 256>>>(x, tx, lnf, nullptr, nullptr, hh, hl, nullptr, nullptr, 1);
    k_gemm_lmw<<<gLM, 256, SMEM_BYTES>>>(out);
}